// round 6
// baseline (speedup 1.0000x reference)
#include <cuda_runtime.h>

#define NN 100000
#define EE 1600000
#define D 64
#define BN_EPS 1e-5f
#define SB 1024
#define NBLK ((NN + SB - 1) / SB)   // 98

// Scratch (device globals — no allocation allowed).
__device__ __align__(16) float g_h [NN * D];
__device__ __align__(16) float g_h1[NN * D];
__device__ __align__(16) float g_sum[D];
__device__ __align__(16) float g_sumsq[D];
__device__ __align__(16) int   g_deg[NN];
__device__ __align__(16) int   g_rowptr[NN + 1];
__device__ __align__(16) int   g_cursor[NN];
__device__ __align__(16) int   g_col[EE];
__device__ __align__(16) int   g_bsum[NBLK];

// ---------------------------------------------------------------------------
// 1: zero degree counters + BN accumulators
// ---------------------------------------------------------------------------
__global__ void k_zero() {
    int i = blockIdx.x * blockDim.x + threadIdx.x;
    if (i < NN) g_deg[i] = 0;
    if (i < D) { g_sum[i] = 0.f; g_sumsq[i] = 0.f; }
}

// ---------------------------------------------------------------------------
// 2: degree histogram over destinations (edge_index is int32)
// ---------------------------------------------------------------------------
__global__ void k_deg(const int* __restrict__ ei) {
    int e = blockIdx.x * blockDim.x + threadIdx.x;
    if (e >= EE) return;
    atomicAdd(&g_deg[ei[EE + e]], 1);
}

// ---------------------------------------------------------------------------
// 3a: per-block degree sums (coalesced, full chip)
// ---------------------------------------------------------------------------
__global__ void __launch_bounds__(SB) k_scan_a() {
    __shared__ int sh[SB];
    int i = blockIdx.x * SB + threadIdx.x;
    sh[threadIdx.x] = (i < NN) ? g_deg[i] : 0;
    __syncthreads();
    for (int off = SB / 2; off > 0; off >>= 1) {
        if (threadIdx.x < off) sh[threadIdx.x] += sh[threadIdx.x + off];
        __syncthreads();
    }
    if (threadIdx.x == 0) g_bsum[blockIdx.x] = sh[0];
}

// ---------------------------------------------------------------------------
// 3b: block-local scan + inline block-offset (scan of 98 sums is redundant
//     per block — cheaper than a dedicated single-block launch)
// ---------------------------------------------------------------------------
__global__ void __launch_bounds__(SB) k_scan_c() {
    __shared__ int sh[SB];
    __shared__ int s_off;
    const int t = threadIdx.x;
    if (t == 0) {
        int off = 0;
        for (int b = 0; b < blockIdx.x; b++) off += g_bsum[b];
        s_off = off;
        if (blockIdx.x == 0) g_rowptr[NN] = EE;
    }
    const int i = blockIdx.x * SB + t;
    const int v = (i < NN) ? g_deg[i] : 0;
    sh[t] = v;
    __syncthreads();
    // Hillis-Steele inclusive scan
    for (int off = 1; off < SB; off <<= 1) {
        int add = (t >= off) ? sh[t - off] : 0;
        __syncthreads();
        sh[t] += add;
        __syncthreads();
    }
    if (i < NN) {
        int excl = s_off + sh[t] - v;
        g_rowptr[i] = excl;
        g_cursor[i] = excl;
    }
}

// ---------------------------------------------------------------------------
// 4: scatter src indices into CSR col array
// ---------------------------------------------------------------------------
__global__ void k_fill(const int* __restrict__ ei) {
    int e = blockIdx.x * blockDim.x + threadIdx.x;
    if (e >= EE) return;
    int src = ei[e];
    int dst = ei[EE + e];
    int pos = atomicAdd(&g_cursor[dst], 1);
    g_col[pos] = src;
}

// ---------------------------------------------------------------------------
// 5: gather. One warp per node; lane owns a float2. 8-way edge unroll:
//    8 independent row loads in flight per lane.
// ---------------------------------------------------------------------------
__global__ void __launch_bounds__(256) k_gather(const float* __restrict__ x,
                                                const float* __restrict__ eps_p) {
    const int w = (blockIdx.x * blockDim.x + threadIdx.x) >> 5;
    const int lane = threadIdx.x & 31;
    if (w >= NN) return;
    const int beg = g_rowptr[w];
    const int end = g_rowptr[w + 1];
    const float2* __restrict__ x2 = (const float2*)x;   // row = 32 float2

    float s0x = 0.f, s0y = 0.f, s1x = 0.f, s1y = 0.f;
    float s2x = 0.f, s2y = 0.f, s3x = 0.f, s3y = 0.f;
    int j = beg;
    for (; j + 7 < end; j += 8) {
        int c0 = g_col[j],     c1 = g_col[j + 1];
        int c2 = g_col[j + 2], c3 = g_col[j + 3];
        int c4 = g_col[j + 4], c5 = g_col[j + 5];
        int c6 = g_col[j + 6], c7 = g_col[j + 7];
        float2 v0 = x2[(size_t)c0 * 32 + lane];
        float2 v1 = x2[(size_t)c1 * 32 + lane];
        float2 v2 = x2[(size_t)c2 * 32 + lane];
        float2 v3 = x2[(size_t)c3 * 32 + lane];
        float2 v4 = x2[(size_t)c4 * 32 + lane];
        float2 v5 = x2[(size_t)c5 * 32 + lane];
        float2 v6 = x2[(size_t)c6 * 32 + lane];
        float2 v7 = x2[(size_t)c7 * 32 + lane];
        s0x += v0.x; s0y += v0.y;  s1x += v1.x; s1y += v1.y;
        s2x += v2.x; s2y += v2.y;  s3x += v3.x; s3y += v3.y;
        s0x += v4.x; s0y += v4.y;  s1x += v5.x; s1y += v5.y;
        s2x += v6.x; s2y += v6.y;  s3x += v7.x; s3y += v7.y;
    }
    for (; j < end; j++) {
        int c0 = g_col[j];
        float2 v0 = x2[(size_t)c0 * 32 + lane];
        s0x += v0.x; s0y += v0.y;
    }
    const float sc = 1.f + *eps_p;
    float2 xv = x2[(size_t)w * 32 + lane];
    float2 o;
    o.x = sc * xv.x + ((s0x + s1x) + (s2x + s3x));
    o.y = sc * xv.y + ((s0y + s1y) + (s2y + s3y));
    ((float2*)g_h)[(size_t)w * 32 + lane] = o;
}

// ---------------------------------------------------------------------------
// 6: h1 = h @ W1 + b1, FUSED with BN-stat accumulation.
//    Each thread owns a full h1 row in registers; per-column warp butterfly
//    reduction gives per-warp sums -> 2*64 atomics per warp.
// ---------------------------------------------------------------------------
__global__ void __launch_bounds__(128) k_gemm1(const float* __restrict__ W1,
                                               const float* __restrict__ b1) {
    __shared__ __align__(16) float Ws[D * D];
    __shared__ __align__(16) float bs[D];
    const int tid = threadIdx.x;
    for (int i = tid; i < D * D; i += blockDim.x) Ws[i] = W1[i];
    if (tid < D) bs[tid] = b1[tid];
    __syncthreads();

    const int row = blockIdx.x * blockDim.x + tid;
    const bool valid = row < NN;

    float acc[D];
#pragma unroll
    for (int j = 0; j < D; j++) acc[j] = 0.f;

    if (valid) {
        const float4* __restrict__ hr = (const float4*)(g_h + (size_t)row * D);
        for (int k4 = 0; k4 < D / 4; k4++) {
            float4 hv = hr[k4];
#pragma unroll
            for (int kk = 0; kk < 4; kk++) {
                const float hk = ((const float*)&hv)[kk];
                const float4* wrow = (const float4*)&Ws[(k4 * 4 + kk) * D];
#pragma unroll
                for (int j4 = 0; j4 < D / 4; j4++) {
                    float4 w = wrow[j4];
                    acc[j4 * 4 + 0] += hk * w.x;
                    acc[j4 * 4 + 1] += hk * w.y;
                    acc[j4 * 4 + 2] += hk * w.z;
                    acc[j4 * 4 + 3] += hk * w.w;
                }
            }
        }
#pragma unroll
        for (int j = 0; j < D; j++) acc[j] += bs[j];

        float4* out = (float4*)(g_h1 + (size_t)row * D);
#pragma unroll
        for (int j4 = 0; j4 < D / 4; j4++) {
            float4 o;
            o.x = acc[j4 * 4 + 0]; o.y = acc[j4 * 4 + 1];
            o.z = acc[j4 * 4 + 2]; o.w = acc[j4 * 4 + 3];
            out[j4] = o;
        }
    }
    // invalid rows contribute zeros to stats
    if (!valid) {
#pragma unroll
        for (int j = 0; j < D; j++) acc[j] = 0.f;
    }

    // warp-level column reduction for BN stats
    const int lane = tid & 31;
#pragma unroll
    for (int j = 0; j < D; j++) {
        float s = acc[j];
        float q = acc[j] * acc[j];
#pragma unroll
        for (int off = 16; off > 0; off >>= 1) {
            s += __shfl_xor_sync(0xffffffffu, s, off);
            q += __shfl_xor_sync(0xffffffffu, q, off);
        }
        if (lane == (j & 31)) {          // spread atomics across lanes
            atomicAdd(&g_sum[j], s);
            atomicAdd(&g_sumsq[j], q);
        }
    }
}

// ---------------------------------------------------------------------------
// 7: out = relu(BN(h1)) @ W2 + b2, BN folded into per-column scale/shift
// ---------------------------------------------------------------------------
__global__ void __launch_bounds__(128) k_gemm2(const float* __restrict__ W2,
                                               const float* __restrict__ b2,
                                               const float* __restrict__ gamma,
                                               const float* __restrict__ beta,
                                               float* __restrict__ out) {
    __shared__ __align__(16) float Ws[D * D];
    __shared__ __align__(16) float scl[D];
    __shared__ __align__(16) float sft[D];
    __shared__ __align__(16) float bs[D];
    const int tid = threadIdx.x;
    for (int i = tid; i < D * D; i += blockDim.x) Ws[i] = W2[i];
    if (tid < D) {
        const float inv_n = 1.f / (float)NN;
        float mean = g_sum[tid] * inv_n;
        float var  = g_sumsq[tid] * inv_n - mean * mean;
        float rstd = rsqrtf(var + BN_EPS);
        float s = rstd * gamma[tid];
        scl[tid] = s;
        sft[tid] = beta[tid] - mean * s;
        bs[tid]  = b2[tid];
    }
    __syncthreads();

    const int row = blockIdx.x * blockDim.x + tid;
    if (row >= NN) return;

    float acc[D];
#pragma unroll
    for (int j = 0; j < D; j++) acc[j] = 0.f;

    const float4* __restrict__ hr = (const float4*)(g_h1 + (size_t)row * D);
    for (int k4 = 0; k4 < D / 4; k4++) {
        float4 hv = hr[k4];
#pragma unroll
        for (int kk = 0; kk < 4; kk++) {
            const int k = k4 * 4 + kk;
            float hk = ((const float*)&hv)[kk];
            hk = fmaxf(hk * scl[k] + sft[k], 0.f);        // BN + ReLU
            const float4* wrow = (const float4*)&Ws[k * D];
#pragma unroll
            for (int j4 = 0; j4 < D / 4; j4++) {
                float4 w = wrow[j4];
                acc[j4 * 4 + 0] += hk * w.x;
                acc[j4 * 4 + 1] += hk * w.y;
                acc[j4 * 4 + 2] += hk * w.z;
                acc[j4 * 4 + 3] += hk * w.w;
            }
        }
    }
    float4* o4 = (float4*)(out + (size_t)row * D);
#pragma unroll
    for (int j4 = 0; j4 < D / 4; j4++) {
        float4 o;
        o.x = acc[j4 * 4 + 0] + bs[j4 * 4 + 0];
        o.y = acc[j4 * 4 + 1] + bs[j4 * 4 + 1];
        o.z = acc[j4 * 4 + 2] + bs[j4 * 4 + 2];
        o.w = acc[j4 * 4 + 3] + bs[j4 * 4 + 3];
        o4[j4] = o;
    }
}

// ---------------------------------------------------------------------------
extern "C" void kernel_launch(void* const* d_in, const int* in_sizes, int n_in,
                              void* d_out, int out_size) {
    const float* x     = (const float*)d_in[0];
    const int*   ei    = (const int*)  d_in[1];   // int32 (JAX demotes int64)
    const float* eps   = (const float*)d_in[2];
    const float* W1    = (const float*)d_in[3];
    const float* b1    = (const float*)d_in[4];
    const float* gamma = (const float*)d_in[5];
    const float* beta  = (const float*)d_in[6];
    const float* W2    = (const float*)d_in[7];
    const float* b2    = (const float*)d_in[8];
    float* out = (float*)d_out;

    k_zero  <<<(NN + 255) / 256, 256>>>();
    k_deg   <<<(EE + 255) / 256, 256>>>(ei);
    k_scan_a<<<NBLK, SB>>>();
    k_scan_c<<<NBLK, SB>>>();
    k_fill  <<<(EE + 255) / 256, 256>>>(ei);
    k_gather<<<(NN * 32 + 255) / 256, 256>>>(x, eps);
    k_gemm1 <<<(NN + 127) / 128, 128>>>(W1, b1);
    k_gemm2 <<<(NN + 127) / 128, 128>>>(W2, b2, gamma, beta, out);
}

// round 7
// speedup vs baseline: 1.9600x; 1.9600x over previous
#include <cuda_runtime.h>

#define NN 100000
#define EE 1600000
#define D 64
#define BN_EPS 1e-5f
#define SB 1024
#define NBLK ((NN + SB - 1) / SB)   // 98

// Scratch (device globals — no allocation allowed).
__device__ __align__(16) float g_h [NN * D];
__device__ __align__(16) float g_h1[NN * D];
__device__ __align__(16) float g_sum[D];
__device__ __align__(16) float g_sumsq[D];
__device__ __align__(16) int   g_deg[NN];
__device__ __align__(16) int   g_rowptr[NN + 1];
__device__ __align__(16) int   g_cursor[NN];
__device__ __align__(16) int   g_col[EE];
__device__ __align__(16) int   g_bsum[NBLK];

// ---------------------------------------------------------------------------
// 1: zero degree counters + BN accumulators
// ---------------------------------------------------------------------------
__global__ void k_zero() {
    int i = blockIdx.x * blockDim.x + threadIdx.x;
    if (i < NN) g_deg[i] = 0;
    if (i < D) { g_sum[i] = 0.f; g_sumsq[i] = 0.f; }
}

// ---------------------------------------------------------------------------
// 2: degree histogram over destinations (edge_index is int32)
// ---------------------------------------------------------------------------
__global__ void k_deg(const int* __restrict__ ei) {
    int e = blockIdx.x * blockDim.x + threadIdx.x;
    if (e >= EE) return;
    atomicAdd(&g_deg[ei[EE + e]], 1);
}

// ---------------------------------------------------------------------------
// 3a: per-block degree sums (coalesced, full chip)
// ---------------------------------------------------------------------------
__global__ void __launch_bounds__(SB) k_scan_a() {
    __shared__ int sh[SB];
    int i = blockIdx.x * SB + threadIdx.x;
    sh[threadIdx.x] = (i < NN) ? g_deg[i] : 0;
    __syncthreads();
    for (int off = SB / 2; off > 0; off >>= 1) {
        if (threadIdx.x < off) sh[threadIdx.x] += sh[threadIdx.x + off];
        __syncthreads();
    }
    if (threadIdx.x == 0) g_bsum[blockIdx.x] = sh[0];
}

// ---------------------------------------------------------------------------
// 3b: block-local scan + inline block-offset
// ---------------------------------------------------------------------------
__global__ void __launch_bounds__(SB) k_scan_c() {
    __shared__ int sh[SB];
    __shared__ int s_off;
    const int t = threadIdx.x;
    if (t == 0) {
        int off = 0;
        for (int b = 0; b < blockIdx.x; b++) off += g_bsum[b];
        s_off = off;
        if (blockIdx.x == 0) g_rowptr[NN] = EE;
    }
    const int i = blockIdx.x * SB + t;
    const int v = (i < NN) ? g_deg[i] : 0;
    sh[t] = v;
    __syncthreads();
    // Hillis-Steele inclusive scan
    for (int off = 1; off < SB; off <<= 1) {
        int add = (t >= off) ? sh[t - off] : 0;
        __syncthreads();
        sh[t] += add;
        __syncthreads();
    }
    if (i < NN) {
        int excl = s_off + sh[t] - v;
        g_rowptr[i] = excl;
        g_cursor[i] = excl;
    }
}

// ---------------------------------------------------------------------------
// 4: scatter src indices into CSR col array
// ---------------------------------------------------------------------------
__global__ void k_fill(const int* __restrict__ ei) {
    int e = blockIdx.x * blockDim.x + threadIdx.x;
    if (e >= EE) return;
    int src = ei[e];
    int dst = ei[EE + e];
    int pos = atomicAdd(&g_cursor[dst], 1);
    g_col[pos] = src;
}

// ---------------------------------------------------------------------------
// 5: gather. One warp per node; lane owns a float2. 8-way edge unroll.
// ---------------------------------------------------------------------------
__global__ void __launch_bounds__(256) k_gather(const float* __restrict__ x,
                                                const float* __restrict__ eps_p) {
    const int w = (blockIdx.x * blockDim.x + threadIdx.x) >> 5;
    const int lane = threadIdx.x & 31;
    if (w >= NN) return;
    const int beg = g_rowptr[w];
    const int end = g_rowptr[w + 1];
    const float2* __restrict__ x2 = (const float2*)x;   // row = 32 float2

    float s0x = 0.f, s0y = 0.f, s1x = 0.f, s1y = 0.f;
    float s2x = 0.f, s2y = 0.f, s3x = 0.f, s3y = 0.f;
    int j = beg;
    for (; j + 7 < end; j += 8) {
        int c0 = g_col[j],     c1 = g_col[j + 1];
        int c2 = g_col[j + 2], c3 = g_col[j + 3];
        int c4 = g_col[j + 4], c5 = g_col[j + 5];
        int c6 = g_col[j + 6], c7 = g_col[j + 7];
        float2 v0 = x2[(size_t)c0 * 32 + lane];
        float2 v1 = x2[(size_t)c1 * 32 + lane];
        float2 v2 = x2[(size_t)c2 * 32 + lane];
        float2 v3 = x2[(size_t)c3 * 32 + lane];
        float2 v4 = x2[(size_t)c4 * 32 + lane];
        float2 v5 = x2[(size_t)c5 * 32 + lane];
        float2 v6 = x2[(size_t)c6 * 32 + lane];
        float2 v7 = x2[(size_t)c7 * 32 + lane];
        s0x += v0.x; s0y += v0.y;  s1x += v1.x; s1y += v1.y;
        s2x += v2.x; s2y += v2.y;  s3x += v3.x; s3y += v3.y;
        s0x += v4.x; s0y += v4.y;  s1x += v5.x; s1y += v5.y;
        s2x += v6.x; s2y += v6.y;  s3x += v7.x; s3y += v7.y;
    }
    for (; j < end; j++) {
        int c0 = g_col[j];
        float2 v0 = x2[(size_t)c0 * 32 + lane];
        s0x += v0.x; s0y += v0.y;
    }
    const float sc = 1.f + *eps_p;
    float2 xv = x2[(size_t)w * 32 + lane];
    float2 o;
    o.x = sc * xv.x + ((s0x + s1x) + (s2x + s3x));
    o.y = sc * xv.y + ((s0y + s1y) + (s2y + s3y));
    ((float2*)g_h)[(size_t)w * 32 + lane] = o;
}

// ---------------------------------------------------------------------------
// 6: h1 = h @ W1 + b1. One row per thread, W1 in shared (broadcast LDS).
//    (Plain version — R6's in-GEMM shuffle stats was a 640-SHFL storm.)
// ---------------------------------------------------------------------------
__global__ void __launch_bounds__(128) k_gemm1(const float* __restrict__ W1,
                                               const float* __restrict__ b1) {
    __shared__ __align__(16) float Ws[D * D];
    __shared__ __align__(16) float bs[D];
    const int tid = threadIdx.x;
    for (int i = tid; i < D * D; i += blockDim.x) Ws[i] = W1[i];
    if (tid < D) bs[tid] = b1[tid];
    __syncthreads();

    const int row = blockIdx.x * blockDim.x + tid;
    if (row >= NN) return;

    float acc[D];
#pragma unroll
    for (int j = 0; j < D; j++) acc[j] = 0.f;

    const float4* __restrict__ hr = (const float4*)(g_h + (size_t)row * D);
    for (int k4 = 0; k4 < D / 4; k4++) {
        float4 hv = hr[k4];
#pragma unroll
        for (int kk = 0; kk < 4; kk++) {
            const float hk = ((const float*)&hv)[kk];
            const float4* wrow = (const float4*)&Ws[(k4 * 4 + kk) * D];
#pragma unroll
            for (int j4 = 0; j4 < D / 4; j4++) {
                float4 w = wrow[j4];
                acc[j4 * 4 + 0] += hk * w.x;
                acc[j4 * 4 + 1] += hk * w.y;
                acc[j4 * 4 + 2] += hk * w.z;
                acc[j4 * 4 + 3] += hk * w.w;
            }
        }
    }
    float4* out = (float4*)(g_h1 + (size_t)row * D);
#pragma unroll
    for (int j4 = 0; j4 < D / 4; j4++) {
        float4 o;
        o.x = acc[j4 * 4 + 0] + bs[j4 * 4 + 0];
        o.y = acc[j4 * 4 + 1] + bs[j4 * 4 + 1];
        o.z = acc[j4 * 4 + 2] + bs[j4 * 4 + 2];
        o.w = acc[j4 * 4 + 3] + bs[j4 * 4 + 3];
        out[j4] = o;
    }
}

// ---------------------------------------------------------------------------
// 7: per-column sum / sumsq of h1 (standalone, coalesced, L2-resident)
// ---------------------------------------------------------------------------
__global__ void k_stats() {
    const int col = threadIdx.x & (D - 1);
    const int rib = threadIdx.x >> 6;
    const int stride = (blockDim.x / D) * gridDim.x;
    float s = 0.f, sq = 0.f;
    for (int r = blockIdx.x * (blockDim.x / D) + rib; r < NN; r += stride) {
        float v = g_h1[(size_t)r * D + col];
        s += v; sq += v * v;
    }
    __shared__ __align__(16) float sh[256];
    __shared__ __align__(16) float shq[256];
    sh[threadIdx.x] = s; shq[threadIdx.x] = sq;
    __syncthreads();
    if (threadIdx.x < D) {
        float ts = sh[threadIdx.x] + sh[threadIdx.x + 64] +
                   sh[threadIdx.x + 128] + sh[threadIdx.x + 192];
        float tq = shq[threadIdx.x] + shq[threadIdx.x + 64] +
                   shq[threadIdx.x + 128] + shq[threadIdx.x + 192];
        atomicAdd(&g_sum[threadIdx.x], ts);
        atomicAdd(&g_sumsq[threadIdx.x], tq);
    }
}

// ---------------------------------------------------------------------------
// 8: out = relu(BN(h1)) @ W2 + b2, BN folded into per-column scale/shift
// ---------------------------------------------------------------------------
__global__ void __launch_bounds__(128) k_gemm2(const float* __restrict__ W2,
                                               const float* __restrict__ b2,
                                               const float* __restrict__ gamma,
                                               const float* __restrict__ beta,
                                               float* __restrict__ out) {
    __shared__ __align__(16) float Ws[D * D];
    __shared__ __align__(16) float scl[D];
    __shared__ __align__(16) float sft[D];
    __shared__ __align__(16) float bs[D];
    const int tid = threadIdx.x;
    for (int i = tid; i < D * D; i += blockDim.x) Ws[i] = W2[i];
    if (tid < D) {
        const float inv_n = 1.f / (float)NN;
        float mean = g_sum[tid] * inv_n;
        float var  = g_sumsq[tid] * inv_n - mean * mean;
        float rstd = rsqrtf(var + BN_EPS);
        float s = rstd * gamma[tid];
        scl[tid] = s;
        sft[tid] = beta[tid] - mean * s;
        bs[tid]  = b2[tid];
    }
    __syncthreads();

    const int row = blockIdx.x * blockDim.x + tid;
    if (row >= NN) return;

    float acc[D];
#pragma unroll
    for (int j = 0; j < D; j++) acc[j] = 0.f;

    const float4* __restrict__ hr = (const float4*)(g_h1 + (size_t)row * D);
    for (int k4 = 0; k4 < D / 4; k4++) {
        float4 hv = hr[k4];
#pragma unroll
        for (int kk = 0; kk < 4; kk++) {
            const int k = k4 * 4 + kk;
            float hk = ((const float*)&hv)[kk];
            hk = fmaxf(hk * scl[k] + sft[k], 0.f);        // BN + ReLU
            const float4* wrow = (const float4*)&Ws[k * D];
#pragma unroll
            for (int j4 = 0; j4 < D / 4; j4++) {
                float4 w = wrow[j4];
                acc[j4 * 4 + 0] += hk * w.x;
                acc[j4 * 4 + 1] += hk * w.y;
                acc[j4 * 4 + 2] += hk * w.z;
                acc[j4 * 4 + 3] += hk * w.w;
            }
        }
    }
    float4* o4 = (float4*)(out + (size_t)row * D);
#pragma unroll
    for (int j4 = 0; j4 < D / 4; j4++) {
        float4 o;
        o.x = acc[j4 * 4 + 0] + bs[j4 * 4 + 0];
        o.y = acc[j4 * 4 + 1] + bs[j4 * 4 + 1];
        o.z = acc[j4 * 4 + 2] + bs[j4 * 4 + 2];
        o.w = acc[j4 * 4 + 3] + bs[j4 * 4 + 3];
        o4[j4] = o;
    }
}

// ---------------------------------------------------------------------------
extern "C" void kernel_launch(void* const* d_in, const int* in_sizes, int n_in,
                              void* d_out, int out_size) {
    const float* x     = (const float*)d_in[0];
    const int*   ei    = (const int*)  d_in[1];   // int32 (JAX demotes int64)
    const float* eps   = (const float*)d_in[2];
    const float* W1    = (const float*)d_in[3];
    const float* b1    = (const float*)d_in[4];
    const float* gamma = (const float*)d_in[5];
    const float* beta  = (const float*)d_in[6];
    const float* W2    = (const float*)d_in[7];
    const float* b2    = (const float*)d_in[8];
    float* out = (float*)d_out;

    k_zero  <<<(NN + 255) / 256, 256>>>();
    k_deg   <<<(EE + 255) / 256, 256>>>(ei);
    k_scan_a<<<NBLK, SB>>>();
    k_scan_c<<<NBLK, SB>>>();
    k_fill  <<<(EE + 255) / 256, 256>>>(ei);
    k_gather<<<(NN * 32 + 255) / 256, 256>>>(x, eps);
    k_gemm1 <<<(NN + 127) / 128, 128>>>(W1, b1);
    k_stats <<<256, 256>>>();
    k_gemm2 <<<(NN + 127) / 128, 128>>>(W2, b2, gamma, beta, out);
}

// round 8
// speedup vs baseline: 1.9828x; 1.0117x over previous
#include <cuda_runtime.h>

#define NN 100000
#define EE 1600000
#define D 64
#define BN_EPS 1e-5f
#define SB 1024
#define NBLK ((NN + SB - 1) / SB)   // 98

// Packed f32x2 FMA (Blackwell): d = a*b + c per 32-bit lane.
// ptxas never emits FFMA2 from C++ — PTX-only (SASS_QUICKREF).
#define FMA_F32X2(d, a, b, c) \
    asm("fma.rn.f32x2 %0, %1, %2, %3;" : "=l"(d) : "l"(a), "l"(b), "l"(c))
#define PACK_F32X2(out, lo, hi) \
    asm("mov.b64 %0, {%1, %2};" : "=l"(out) : "f"(lo), "f"(hi))
#define UNPACK_F32X2(lo, hi, in) \
    asm("mov.b64 {%0, %1}, %2;" : "=f"(lo), "=f"(hi) : "l"(in))

// Scratch (device globals — no allocation allowed).
__device__ __align__(16) float g_h [NN * D];
__device__ __align__(16) float g_h1[NN * D];
__device__ __align__(16) float g_sum[D];
__device__ __align__(16) float g_sumsq[D];
__device__ __align__(16) int   g_deg[NN];
__device__ __align__(16) int   g_rowptr[NN + 1];
__device__ __align__(16) int   g_cursor[NN];
__device__ __align__(16) int   g_col[EE];
__device__ __align__(16) int   g_bsum[NBLK];

// ---------------------------------------------------------------------------
// 1: zero degree counters + BN accumulators
// ---------------------------------------------------------------------------
__global__ void k_zero() {
    int i = blockIdx.x * blockDim.x + threadIdx.x;
    if (i < NN) g_deg[i] = 0;
    if (i < D) { g_sum[i] = 0.f; g_sumsq[i] = 0.f; }
}

// ---------------------------------------------------------------------------
// 2: degree histogram over destinations (edge_index is int32)
// ---------------------------------------------------------------------------
__global__ void k_deg(const int* __restrict__ ei) {
    int e = blockIdx.x * blockDim.x + threadIdx.x;
    if (e >= EE) return;
    atomicAdd(&g_deg[ei[EE + e]], 1);
}

// ---------------------------------------------------------------------------
// 3a: per-block degree sums
// ---------------------------------------------------------------------------
__global__ void __launch_bounds__(SB) k_scan_a() {
    __shared__ int sh[SB];
    int i = blockIdx.x * SB + threadIdx.x;
    sh[threadIdx.x] = (i < NN) ? g_deg[i] : 0;
    __syncthreads();
    for (int off = SB / 2; off > 0; off >>= 1) {
        if (threadIdx.x < off) sh[threadIdx.x] += sh[threadIdx.x + off];
        __syncthreads();
    }
    if (threadIdx.x == 0) g_bsum[blockIdx.x] = sh[0];
}

// ---------------------------------------------------------------------------
// 3b: block-local scan + inline block-offset
// ---------------------------------------------------------------------------
__global__ void __launch_bounds__(SB) k_scan_c() {
    __shared__ int sh[SB];
    __shared__ int s_off;
    const int t = threadIdx.x;
    if (t == 0) {
        int off = 0;
        for (int b = 0; b < blockIdx.x; b++) off += g_bsum[b];
        s_off = off;
        if (blockIdx.x == 0) g_rowptr[NN] = EE;
    }
    const int i = blockIdx.x * SB + t;
    const int v = (i < NN) ? g_deg[i] : 0;
    sh[t] = v;
    __syncthreads();
    for (int off = 1; off < SB; off <<= 1) {
        int add = (t >= off) ? sh[t - off] : 0;
        __syncthreads();
        sh[t] += add;
        __syncthreads();
    }
    if (i < NN) {
        int excl = s_off + sh[t] - v;
        g_rowptr[i] = excl;
        g_cursor[i] = excl;
    }
}

// ---------------------------------------------------------------------------
// 4: scatter src indices into CSR col array
// ---------------------------------------------------------------------------
__global__ void k_fill(const int* __restrict__ ei) {
    int e = blockIdx.x * blockDim.x + threadIdx.x;
    if (e >= EE) return;
    int src = ei[e];
    int dst = ei[EE + e];
    int pos = atomicAdd(&g_cursor[dst], 1);
    g_col[pos] = src;
}

// ---------------------------------------------------------------------------
// 5: gather. One warp per node; lane owns a float2. 8-way edge unroll.
// ---------------------------------------------------------------------------
__global__ void __launch_bounds__(256) k_gather(const float* __restrict__ x,
                                                const float* __restrict__ eps_p) {
    const int w = (blockIdx.x * blockDim.x + threadIdx.x) >> 5;
    const int lane = threadIdx.x & 31;
    if (w >= NN) return;
    const int beg = g_rowptr[w];
    const int end = g_rowptr[w + 1];
    const float2* __restrict__ x2 = (const float2*)x;   // row = 32 float2

    float s0x = 0.f, s0y = 0.f, s1x = 0.f, s1y = 0.f;
    float s2x = 0.f, s2y = 0.f, s3x = 0.f, s3y = 0.f;
    int j = beg;
    for (; j + 7 < end; j += 8) {
        int c0 = g_col[j],     c1 = g_col[j + 1];
        int c2 = g_col[j + 2], c3 = g_col[j + 3];
        int c4 = g_col[j + 4], c5 = g_col[j + 5];
        int c6 = g_col[j + 6], c7 = g_col[j + 7];
        float2 v0 = x2[(size_t)c0 * 32 + lane];
        float2 v1 = x2[(size_t)c1 * 32 + lane];
        float2 v2 = x2[(size_t)c2 * 32 + lane];
        float2 v3 = x2[(size_t)c3 * 32 + lane];
        float2 v4 = x2[(size_t)c4 * 32 + lane];
        float2 v5 = x2[(size_t)c5 * 32 + lane];
        float2 v6 = x2[(size_t)c6 * 32 + lane];
        float2 v7 = x2[(size_t)c7 * 32 + lane];
        s0x += v0.x; s0y += v0.y;  s1x += v1.x; s1y += v1.y;
        s2x += v2.x; s2y += v2.y;  s3x += v3.x; s3y += v3.y;
        s0x += v4.x; s0y += v4.y;  s1x += v5.x; s1y += v5.y;
        s2x += v6.x; s2y += v6.y;  s3x += v7.x; s3y += v7.y;
    }
    for (; j < end; j++) {
        int c0 = g_col[j];
        float2 v0 = x2[(size_t)c0 * 32 + lane];
        s0x += v0.x; s0y += v0.y;
    }
    const float sc = 1.f + *eps_p;
    float2 xv = x2[(size_t)w * 32 + lane];
    float2 o;
    o.x = sc * xv.x + ((s0x + s1x) + (s2x + s3x));
    o.y = sc * xv.y + ((s0y + s1y) + (s2y + s3y));
    ((float2*)g_h)[(size_t)w * 32 + lane] = o;
}

// ---------------------------------------------------------------------------
// 6: h1 = h @ W1 + b1. One row per thread; accumulators are f32x2 pairs,
//    inner product done with packed fma.rn.f32x2 (FFMA2) — halves FFMA count.
// ---------------------------------------------------------------------------
__global__ void __launch_bounds__(128) k_gemm1(const float* __restrict__ W1,
                                               const float* __restrict__ b1) {
    __shared__ __align__(16) float Ws[D * D];
    __shared__ __align__(16) float bs[D];
    const int tid = threadIdx.x;
    for (int i = tid; i < D * D; i += blockDim.x) Ws[i] = W1[i];
    if (tid < D) bs[tid] = b1[tid];
    __syncthreads();

    const int row = blockIdx.x * blockDim.x + tid;
    if (row >= NN) return;

    // 32 packed accumulators = 64 output columns, seeded with the bias
    unsigned long long acc2[D / 2];
    const unsigned long long* bs2 = (const unsigned long long*)bs;
#pragma unroll
    for (int j = 0; j < D / 2; j++) acc2[j] = bs2[j];

    const float4* __restrict__ hr = (const float4*)(g_h + (size_t)row * D);
    for (int k4 = 0; k4 < D / 4; k4++) {
        float4 hv = hr[k4];
#pragma unroll
        for (int kk = 0; kk < 4; kk++) {
            const float hk = ((const float*)&hv)[kk];
            unsigned long long hk2;
            PACK_F32X2(hk2, hk, hk);
            const ulonglong2* wrow =
                (const ulonglong2*)&Ws[(k4 * 4 + kk) * D];
#pragma unroll
            for (int j8 = 0; j8 < D / 8; j8++) {      // 8 cols = 4 f32x2 per 2 LDS.128
                ulonglong2 wv0 = wrow[j8 * 2];
                ulonglong2 wv1 = wrow[j8 * 2 + 1];
                FMA_F32X2(acc2[j8 * 4 + 0], hk2, wv0.x, acc2[j8 * 4 + 0]);
                FMA_F32X2(acc2[j8 * 4 + 1], hk2, wv0.y, acc2[j8 * 4 + 1]);
                FMA_F32X2(acc2[j8 * 4 + 2], hk2, wv1.x, acc2[j8 * 4 + 2]);
                FMA_F32X2(acc2[j8 * 4 + 3], hk2, wv1.y, acc2[j8 * 4 + 3]);
            }
        }
    }
    ulonglong2* out = (ulonglong2*)(g_h1 + (size_t)row * D);
#pragma unroll
    for (int j4 = 0; j4 < D / 4; j4++) {
        ulonglong2 o;
        o.x = acc2[j4 * 2];
        o.y = acc2[j4 * 2 + 1];
        out[j4] = o;
    }
}

// ---------------------------------------------------------------------------
// 7: per-column sum / sumsq of h1 (coalesced, L2-resident)
// ---------------------------------------------------------------------------
__global__ void k_stats() {
    const int col = threadIdx.x & (D - 1);
    const int rib = threadIdx.x >> 6;
    const int stride = (blockDim.x / D) * gridDim.x;
    float s = 0.f, sq = 0.f;
    for (int r = blockIdx.x * (blockDim.x / D) + rib; r < NN; r += stride) {
        float v = g_h1[(size_t)r * D + col];
        s += v; sq += v * v;
    }
    __shared__ __align__(16) float sh[256];
    __shared__ __align__(16) float shq[256];
    sh[threadIdx.x] = s; shq[threadIdx.x] = sq;
    __syncthreads();
    if (threadIdx.x < D) {
        float ts = sh[threadIdx.x] + sh[threadIdx.x + 64] +
                   sh[threadIdx.x + 128] + sh[threadIdx.x + 192];
        float tq = shq[threadIdx.x] + shq[threadIdx.x + 64] +
                   shq[threadIdx.x + 128] + shq[threadIdx.x + 192];
        atomicAdd(&g_sum[threadIdx.x], ts);
        atomicAdd(&g_sumsq[threadIdx.x], tq);
    }
}

// ---------------------------------------------------------------------------
// 8: out = relu(BN(h1)) @ W2 + b2 — f32x2 inner product, BN folded into
//    per-column scale/shift applied to hk before packing.
// ---------------------------------------------------------------------------
__global__ void __launch_bounds__(128) k_gemm2(const float* __restrict__ W2,
                                               const float* __restrict__ b2,
                                               const float* __restrict__ gamma,
                                               const float* __restrict__ beta,
                                               float* __restrict__ out) {
    __shared__ __align__(16) float Ws[D * D];
    __shared__ __align__(16) float scl[D];
    __shared__ __align__(16) float sft[D];
    __shared__ __align__(16) float bs[D];
    const int tid = threadIdx.x;
    for (int i = tid; i < D * D; i += blockDim.x) Ws[i] = W2[i];
    if (tid < D) {
        const float inv_n = 1.f / (float)NN;
        float mean = g_sum[tid] * inv_n;
        float var  = g_sumsq[tid] * inv_n - mean * mean;
        float rstd = rsqrtf(var + BN_EPS);
        float s = rstd * gamma[tid];
        scl[tid] = s;
        sft[tid] = beta[tid] - mean * s;
        bs[tid]  = b2[tid];
    }
    __syncthreads();

    const int row = blockIdx.x * blockDim.x + tid;
    if (row >= NN) return;

    unsigned long long acc2[D / 2];
    const unsigned long long* bs2 = (const unsigned long long*)bs;
#pragma unroll
    for (int j = 0; j < D / 2; j++) acc2[j] = bs2[j];

    const float4* __restrict__ hr = (const float4*)(g_h1 + (size_t)row * D);
    for (int k4 = 0; k4 < D / 4; k4++) {
        float4 hv = hr[k4];
#pragma unroll
        for (int kk = 0; kk < 4; kk++) {
            const int k = k4 * 4 + kk;
            float hk = ((const float*)&hv)[kk];
            hk = fmaxf(hk * scl[k] + sft[k], 0.f);        // BN + ReLU
            unsigned long long hk2;
            PACK_F32X2(hk2, hk, hk);
            const ulonglong2* wrow = (const ulonglong2*)&Ws[k * D];
#pragma unroll
            for (int j8 = 0; j8 < D / 8; j8++) {
                ulonglong2 wv0 = wrow[j8 * 2];
                ulonglong2 wv1 = wrow[j8 * 2 + 1];
                FMA_F32X2(acc2[j8 * 4 + 0], hk2, wv0.x, acc2[j8 * 4 + 0]);
                FMA_F32X2(acc2[j8 * 4 + 1], hk2, wv0.y, acc2[j8 * 4 + 1]);
                FMA_F32X2(acc2[j8 * 4 + 2], hk2, wv1.x, acc2[j8 * 4 + 2]);
                FMA_F32X2(acc2[j8 * 4 + 3], hk2, wv1.y, acc2[j8 * 4 + 3]);
            }
        }
    }
    ulonglong2* o4 = (ulonglong2*)(out + (size_t)row * D);
#pragma unroll
    for (int j4 = 0; j4 < D / 4; j4++) {
        ulonglong2 o;
        o.x = acc2[j4 * 2];
        o.y = acc2[j4 * 2 + 1];
        o4[j4] = o;
    }
}

// ---------------------------------------------------------------------------
extern "C" void kernel_launch(void* const* d_in, const int* in_sizes, int n_in,
                              void* d_out, int out_size) {
    const float* x     = (const float*)d_in[0];
    const int*   ei    = (const int*)  d_in[1];   // int32 (JAX demotes int64)
    const float* eps   = (const float*)d_in[2];
    const float* W1    = (const float*)d_in[3];
    const float* b1    = (const float*)d_in[4];
    const float* gamma = (const float*)d_in[5];
    const float* beta  = (const float*)d_in[6];
    const float* W2    = (const float*)d_in[7];
    const float* b2    = (const float*)d_in[8];
    float* out = (float*)d_out;

    k_zero  <<<(NN + 255) / 256, 256>>>();
    k_deg   <<<(EE + 255) / 256, 256>>>(ei);
    k_scan_a<<<NBLK, SB>>>();
    k_scan_c<<<NBLK, SB>>>();
    k_fill  <<<(EE + 255) / 256, 256>>>(ei);
    k_gather<<<(NN * 32 + 255) / 256, 256>>>(x, eps);
    k_gemm1 <<<(NN + 127) / 128, 128>>>(W1, b1);
    k_stats <<<256, 256>>>();
    k_gemm2 <<<(NN + 127) / 128, 128>>>(W2, b2, gamma, beta, out);
}

// round 9
// speedup vs baseline: 2.0850x; 1.0515x over previous
#include <cuda_runtime.h>

#define NN 100000
#define EE 1600000
#define D 64
#define BN_EPS 1e-5f
#define SB 1024
#define NBLK ((NN + SB - 1) / SB)   // 98
#define RPAD 66                     // padded row (floats) for the stat reduction

// Packed f32x2 FMA (Blackwell): d = a*b + c per 32-bit lane. PTX-only.
#define FMA_F32X2(d, a, b, c) \
    asm("fma.rn.f32x2 %0, %1, %2, %3;" : "=l"(d) : "l"(a), "l"(b), "l"(c))
#define PACK_F32X2(out, lo, hi) \
    asm("mov.b64 %0, {%1, %2};" : "=l"(out) : "f"(lo), "f"(hi))

// Scratch (device globals — no allocation allowed).
__device__ __align__(16) float g_h [NN * D];
__device__ __align__(16) float g_h1[NN * D];
__device__ __align__(16) float g_sum[D];
__device__ __align__(16) float g_sumsq[D];
__device__ __align__(16) int   g_deg[NN];
__device__ __align__(16) int   g_rowptr[NN + 1];
__device__ __align__(16) int   g_cursor[NN];
__device__ __align__(16) int   g_col[EE];
__device__ __align__(16) int   g_bsum[NBLK];

// ---------------------------------------------------------------------------
// 1: zero degree counters + BN accumulators
// ---------------------------------------------------------------------------
__global__ void k_zero() {
    int i = blockIdx.x * blockDim.x + threadIdx.x;
    if (i < NN) g_deg[i] = 0;
    if (i < D) { g_sum[i] = 0.f; g_sumsq[i] = 0.f; }
}

// ---------------------------------------------------------------------------
// 2: degree histogram (4 edges per thread, int4 load)
// ---------------------------------------------------------------------------
__global__ void k_deg(const int* __restrict__ ei) {
    int e4 = blockIdx.x * blockDim.x + threadIdx.x;
    if (e4 >= EE / 4) return;
    int4 d = ((const int4*)(ei + EE))[e4];
    atomicAdd(&g_deg[d.x], 1);
    atomicAdd(&g_deg[d.y], 1);
    atomicAdd(&g_deg[d.z], 1);
    atomicAdd(&g_deg[d.w], 1);
}

// ---------------------------------------------------------------------------
// 3a: per-block degree sums
// ---------------------------------------------------------------------------
__global__ void __launch_bounds__(SB) k_scan_a() {
    __shared__ int sh[SB];
    int i = blockIdx.x * SB + threadIdx.x;
    sh[threadIdx.x] = (i < NN) ? g_deg[i] : 0;
    __syncthreads();
    for (int off = SB / 2; off > 0; off >>= 1) {
        if (threadIdx.x < off) sh[threadIdx.x] += sh[threadIdx.x + off];
        __syncthreads();
    }
    if (threadIdx.x == 0) g_bsum[blockIdx.x] = sh[0];
}

// ---------------------------------------------------------------------------
// 3b: block-local scan + inline block-offset
// ---------------------------------------------------------------------------
__global__ void __launch_bounds__(SB) k_scan_c() {
    __shared__ int sh[SB];
    __shared__ int s_off;
    const int t = threadIdx.x;
    if (t == 0) {
        int off = 0;
        for (int b = 0; b < blockIdx.x; b++) off += g_bsum[b];
        s_off = off;
        if (blockIdx.x == 0) g_rowptr[NN] = EE;
    }
    const int i = blockIdx.x * SB + t;
    const int v = (i < NN) ? g_deg[i] : 0;
    sh[t] = v;
    __syncthreads();
    for (int off = 1; off < SB; off <<= 1) {
        int add = (t >= off) ? sh[t - off] : 0;
        __syncthreads();
        sh[t] += add;
        __syncthreads();
    }
    if (i < NN) {
        int excl = s_off + sh[t] - v;
        g_rowptr[i] = excl;
        g_cursor[i] = excl;
    }
}

// ---------------------------------------------------------------------------
// 4: scatter src into CSR col (4 edges per thread, int4 loads)
// ---------------------------------------------------------------------------
__global__ void k_fill(const int* __restrict__ ei) {
    int e4 = blockIdx.x * blockDim.x + threadIdx.x;
    if (e4 >= EE / 4) return;
    int4 s = ((const int4*)ei)[e4];
    int4 d = ((const int4*)(ei + EE))[e4];
    g_col[atomicAdd(&g_cursor[d.x], 1)] = s.x;
    g_col[atomicAdd(&g_cursor[d.y], 1)] = s.y;
    g_col[atomicAdd(&g_cursor[d.z], 1)] = s.z;
    g_col[atomicAdd(&g_cursor[d.w], 1)] = s.w;
}

// ---------------------------------------------------------------------------
// 5: gather. One warp per node; lane owns a float2. 8-way edge unroll.
// ---------------------------------------------------------------------------
__global__ void __launch_bounds__(256) k_gather(const float* __restrict__ x,
                                                const float* __restrict__ eps_p) {
    const int w = (blockIdx.x * blockDim.x + threadIdx.x) >> 5;
    const int lane = threadIdx.x & 31;
    if (w >= NN) return;
    const int beg = g_rowptr[w];
    const int end = g_rowptr[w + 1];
    const float2* __restrict__ x2 = (const float2*)x;   // row = 32 float2

    float s0x = 0.f, s0y = 0.f, s1x = 0.f, s1y = 0.f;
    float s2x = 0.f, s2y = 0.f, s3x = 0.f, s3y = 0.f;
    int j = beg;
    for (; j + 7 < end; j += 8) {
        int c0 = g_col[j],     c1 = g_col[j + 1];
        int c2 = g_col[j + 2], c3 = g_col[j + 3];
        int c4 = g_col[j + 4], c5 = g_col[j + 5];
        int c6 = g_col[j + 6], c7 = g_col[j + 7];
        float2 v0 = x2[(size_t)c0 * 32 + lane];
        float2 v1 = x2[(size_t)c1 * 32 + lane];
        float2 v2 = x2[(size_t)c2 * 32 + lane];
        float2 v3 = x2[(size_t)c3 * 32 + lane];
        float2 v4 = x2[(size_t)c4 * 32 + lane];
        float2 v5 = x2[(size_t)c5 * 32 + lane];
        float2 v6 = x2[(size_t)c6 * 32 + lane];
        float2 v7 = x2[(size_t)c7 * 32 + lane];
        s0x += v0.x; s0y += v0.y;  s1x += v1.x; s1y += v1.y;
        s2x += v2.x; s2y += v2.y;  s3x += v3.x; s3y += v3.y;
        s0x += v4.x; s0y += v4.y;  s1x += v5.x; s1y += v5.y;
        s2x += v6.x; s2y += v6.y;  s3x += v7.x; s3y += v7.y;
    }
    for (; j < end; j++) {
        int c0 = g_col[j];
        float2 v0 = x2[(size_t)c0 * 32 + lane];
        s0x += v0.x; s0y += v0.y;
    }
    const float sc = 1.f + *eps_p;
    float2 xv = x2[(size_t)w * 32 + lane];
    float2 o;
    o.x = sc * xv.x + ((s0x + s1x) + (s2x + s3x));
    o.y = sc * xv.y + ((s0y + s1y) + (s2y + s3y));
    ((float2*)g_h)[(size_t)w * 32 + lane] = o;
}

// ---------------------------------------------------------------------------
// 6: h1 = h @ W1 + b1 (FFMA2) + fused BN column stats via smem block
//    reduction. Smem pool is time-sliced: W1 during compute, reduction after.
// ---------------------------------------------------------------------------
__global__ void __launch_bounds__(128) k_gemm1(const float* __restrict__ W1,
                                               const float* __restrict__ b1) {
    __shared__ __align__(16) float pool[128 * RPAD];   // 33.8 KB
    float* Ws = pool;                                  // [0, 4096)
    float* bs = pool + D * D;                          // [4096, 4160)
    const int tid = threadIdx.x;
    for (int i = tid; i < D * D; i += blockDim.x) Ws[i] = W1[i];
    if (tid < D) bs[tid] = b1[tid];
    __syncthreads();

    const int row = blockIdx.x * blockDim.x + tid;
    const bool valid = row < NN;

    unsigned long long acc2[D / 2];
    if (valid) {
        const unsigned long long* bs2 = (const unsigned long long*)bs;
#pragma unroll
        for (int j = 0; j < D / 2; j++) acc2[j] = bs2[j];

        const float4* __restrict__ hr = (const float4*)(g_h + (size_t)row * D);
        for (int k4 = 0; k4 < D / 4; k4++) {
            float4 hv = hr[k4];
#pragma unroll
            for (int kk = 0; kk < 4; kk++) {
                const float hk = ((const float*)&hv)[kk];
                unsigned long long hk2;
                PACK_F32X2(hk2, hk, hk);
                const ulonglong2* wrow =
                    (const ulonglong2*)&Ws[(k4 * 4 + kk) * D];
#pragma unroll
                for (int j8 = 0; j8 < D / 8; j8++) {
                    ulonglong2 wv0 = wrow[j8 * 2];
                    ulonglong2 wv1 = wrow[j8 * 2 + 1];
                    FMA_F32X2(acc2[j8 * 4 + 0], hk2, wv0.x, acc2[j8 * 4 + 0]);
                    FMA_F32X2(acc2[j8 * 4 + 1], hk2, wv0.y, acc2[j8 * 4 + 1]);
                    FMA_F32X2(acc2[j8 * 4 + 2], hk2, wv1.x, acc2[j8 * 4 + 2]);
                    FMA_F32X2(acc2[j8 * 4 + 3], hk2, wv1.y, acc2[j8 * 4 + 3]);
                }
            }
        }
        ulonglong2* out = (ulonglong2*)(g_h1 + (size_t)row * D);
#pragma unroll
        for (int j4 = 0; j4 < D / 4; j4++) {
            ulonglong2 o;
            o.x = acc2[j4 * 2];
            o.y = acc2[j4 * 2 + 1];
            out[j4] = o;
        }
    } else {
#pragma unroll
        for (int j = 0; j < D / 2; j++) acc2[j] = 0ull;   // zero contribution
    }

    // --- fused BN stats: block column-reduction through the (now dead) pool
    __syncthreads();                       // everyone done reading Ws/bs
    unsigned long long* red2 = (unsigned long long*)(pool + tid * RPAD);
#pragma unroll
    for (int j = 0; j < D / 2; j++) red2[j] = acc2[j];
    __syncthreads();
    if (tid < D) {
        float s = 0.f, q = 0.f;
        for (int i = 0; i < 128; i++) {
            float v = pool[i * RPAD + tid];
            s += v; q += v * v;
        }
        atomicAdd(&g_sum[tid], s);
        atomicAdd(&g_sumsq[tid], q);
    }
}

// ---------------------------------------------------------------------------
// 7: out = relu(BN(h1)) @ W2 + b2 — f32x2 inner product, BN folded in.
// ---------------------------------------------------------------------------
__global__ void __launch_bounds__(128) k_gemm2(const float* __restrict__ W2,
                                               const float* __restrict__ b2,
                                               const float* __restrict__ gamma,
                                               const float* __restrict__ beta,
                                               float* __restrict__ out) {
    __shared__ __align__(16) float Ws[D * D];
    __shared__ __align__(16) float scl[D];
    __shared__ __align__(16) float sft[D];
    __shared__ __align__(16) float bs[D];
    const int tid = threadIdx.x;
    for (int i = tid; i < D * D; i += blockDim.x) Ws[i] = W2[i];
    if (tid < D) {
        const float inv_n = 1.f / (float)NN;
        float mean = g_sum[tid] * inv_n;
        float var  = g_sumsq[tid] * inv_n - mean * mean;
        float rstd = rsqrtf(var + BN_EPS);
        float s = rstd * gamma[tid];
        scl[tid] = s;
        sft[tid] = beta[tid] - mean * s;
        bs[tid]  = b2[tid];
    }
    __syncthreads();

    const int row = blockIdx.x * blockDim.x + tid;
    if (row >= NN) return;

    unsigned long long acc2[D / 2];
    const unsigned long long* bs2 = (const unsigned long long*)bs;
#pragma unroll
    for (int j = 0; j < D / 2; j++) acc2[j] = bs2[j];

    const float4* __restrict__ hr = (const float4*)(g_h1 + (size_t)row * D);
    for (int k4 = 0; k4 < D / 4; k4++) {
        float4 hv = hr[k4];
#pragma unroll
        for (int kk = 0; kk < 4; kk++) {
            const int k = k4 * 4 + kk;
            float hk = ((const float*)&hv)[kk];
            hk = fmaxf(hk * scl[k] + sft[k], 0.f);        // BN + ReLU
            unsigned long long hk2;
            PACK_F32X2(hk2, hk, hk);
            const ulonglong2* wrow = (const ulonglong2*)&Ws[k * D];
#pragma unroll
            for (int j8 = 0; j8 < D / 8; j8++) {
                ulonglong2 wv0 = wrow[j8 * 2];
                ulonglong2 wv1 = wrow[j8 * 2 + 1];
                FMA_F32X2(acc2[j8 * 4 + 0], hk2, wv0.x, acc2[j8 * 4 + 0]);
                FMA_F32X2(acc2[j8 * 4 + 1], hk2, wv0.y, acc2[j8 * 4 + 1]);
                FMA_F32X2(acc2[j8 * 4 + 2], hk2, wv1.x, acc2[j8 * 4 + 2]);
                FMA_F32X2(acc2[j8 * 4 + 3], hk2, wv1.y, acc2[j8 * 4 + 3]);
            }
        }
    }
    ulonglong2* o4 = (ulonglong2*)(out + (size_t)row * D);
#pragma unroll
    for (int j4 = 0; j4 < D / 4; j4++) {
        ulonglong2 o;
        o.x = acc2[j4 * 2];
        o.y = acc2[j4 * 2 + 1];
        o4[j4] = o;
    }
}

// ---------------------------------------------------------------------------
extern "C" void kernel_launch(void* const* d_in, const int* in_sizes, int n_in,
                              void* d_out, int out_size) {
    const float* x     = (const float*)d_in[0];
    const int*   ei    = (const int*)  d_in[1];   // int32 (JAX demotes int64)
    const float* eps   = (const float*)d_in[2];
    const float* W1    = (const float*)d_in[3];
    const float* b1    = (const float*)d_in[4];
    const float* gamma = (const float*)d_in[5];
    const float* beta  = (const float*)d_in[6];
    const float* W2    = (const float*)d_in[7];
    const float* b2    = (const float*)d_in[8];
    float* out = (float*)d_out;

    k_zero  <<<(NN + 255) / 256, 256>>>();
    k_deg   <<<(EE / 4 + 255) / 256, 256>>>(ei);
    k_scan_a<<<NBLK, SB>>>();
    k_scan_c<<<NBLK, SB>>>();
    k_fill  <<<(EE / 4 + 255) / 256, 256>>>(ei);
    k_gather<<<(NN * 32 + 255) / 256, 256>>>(x, eps);
    k_gemm1 <<<(NN + 127) / 128, 128>>>(W1, b1);
    k_gemm2 <<<(NN + 127) / 128, 128>>>(W2, b2, gamma, beta, out);
}